// round 1
// baseline (speedup 1.0000x reference)
#include <cuda_runtime.h>
#include <cuda_bf16.h>
#include <cstdint>

// Problem constants (fixed by the reference)
constexpr int B_   = 32;
constexpr int C_   = 3;
constexpr int H_   = 512;
constexpr int W_   = 512;
constexpr int OH_  = 128;
constexpr int OW_  = 64;
constexpr int NNZ_ = 98304;

constexpr int HW_   = H_ * W_;          // 262144
constexpr int CHW_  = C_ * HW_;         // 786432  (per-sample x stride)
constexpr int OHW_  = OH_ * OW_;        // 8192
constexpr int COHW_ = C_ * OHW_;        // 24576   (per-sample out stride)
constexpr int RES_  = B_ * COHW_;       // 786432  (result element count)

// Each thread handles 4 consecutive COO entries via 128-bit loads.
constexpr int TPB   = 256;
constexpr int EPT   = 4;
constexpr int GRIDX = NNZ_ / (TPB * EPT);   // 96

__global__ void __launch_bounds__(TPB)
tti_scatter_kernel(const float* __restrict__ x,
                   const int*   __restrict__ rows,
                   const int*   __restrict__ cols,
                   const float* __restrict__ vals,
                   float*       __restrict__ out)
{
    const int b = blockIdx.y;
    const int k = (blockIdx.x * TPB + threadIdx.x) * EPT;
    const long base = (long)b * NNZ_ + k;

    const int4   r4 = *reinterpret_cast<const int4*>(rows + base);
    const int4   c4 = *reinterpret_cast<const int4*>(cols + base);
    const float4 v4 = *reinterpret_cast<const float4*>(vals + base);

    const float* __restrict__ xb = x + (long)b * CHW_;
    float*       __restrict__ ob = out + (long)b * COHW_;

    int cc[EPT] = {c4.x, c4.y, c4.z, c4.w};
    int rr[EPT] = {r4.x, r4.y, r4.z, r4.w};
    float vv[EPT] = {v4.x, v4.y, v4.z, v4.w};

    // Issue all gathers first for MLP (hide DRAM latency).
    float g[EPT];
#pragma unroll
    for (int i = 0; i < EPT; ++i) {
        const int col = cc[i];
        const int hw  = col / 3;            // spatial index (h*W + w)
        const int ch  = col - 3 * hw;       // channel
        g[i] = __ldg(xb + ch * HW_ + hw);
    }

    // Scatter with global atomics (REDG); avg 4 duplicates per address.
#pragma unroll
    for (int i = 0; i < EPT; ++i) {
        const int row = rr[i];
        const int p   = row / 3;            // oh*OW + ow
        const int rc  = row - 3 * p;        // channel
        atomicAdd(ob + rc * OHW_ + p, vv[i] * g[i]);
    }
}

extern "C" void kernel_launch(void* const* d_in, const int* in_sizes, int n_in,
                              void* d_out, int out_size)
{
    const float* x    = (const float*)d_in[0];
    const int*   rows = (const int*)  d_in[1];
    const int*   cols = (const int*)  d_in[2];
    const float* vals = (const float*)d_in[3];
    const float* mask = (const float*)d_in[4];
    float* out = (float*)d_out;

    // Zero the result region (d_out is poisoned to 0xAA before timing).
    cudaMemsetAsync(out, 0, (size_t)RES_ * sizeof(float), 0);

    dim3 grid(GRIDX, B_);
    tti_scatter_kernel<<<grid, TPB>>>(x, rows, cols, vals, out);

    // Second tuple output: mask pass-through, concatenated after the result.
    if (out_size > RES_) {
        size_t mask_elems = (size_t)out_size - RES_;
        cudaMemcpyAsync(out + RES_, mask, mask_elems * sizeof(float),
                        cudaMemcpyDeviceToDevice, 0);
    }
}